// round 5
// baseline (speedup 1.0000x reference)
#include <cuda_runtime.h>
#include <cuda_bf16.h>
#include <cstdint>

// ---------------------------------------------------------------------------
// QGCN forward on GB300 — CSR gather + split-TF32 tensor-core GEMM.
//   GEMM: Y = X @ W via mma.sync.m16n8k8.tf32, 3-pass hi/lo split (~fp32 acc).
//   hi/lo pre-split at SMEM staging, stored interleaved {hi,lo}.
// ---------------------------------------------------------------------------

#define N_NODES 50000
#define N_EDGES 800000

__device__ float  g_bufA[N_NODES * 128];
__device__ float  g_bufB[N_NODES * 128];
__device__ float  g_bufC[N_NODES * 128];
__device__ int    g_deg[N_NODES];
__device__ int    g_indptr[N_NODES];
__device__ int    g_cursor[N_NODES];
__device__ float2 g_edges[N_EDGES];   // {src (bit-cast int), weight}

// ---------------------------------------------------------------------------
// TF32 helpers
// ---------------------------------------------------------------------------
__device__ __forceinline__ uint32_t f2tf32(float x) {
    uint32_t r;
    asm("cvt.rna.tf32.f32 %0, %1;" : "=r"(r) : "f"(x));
    return r;
}
__device__ __forceinline__ float2 tf32_split2(float x) {
    uint32_t hi = f2tf32(x);
    uint32_t lo = f2tf32(x - __uint_as_float(hi));
    return make_float2(__uint_as_float(hi), __uint_as_float(lo));
}
__device__ __forceinline__ void mma_tf32(
    float& d0, float& d1, float& d2, float& d3,
    uint32_t a0, uint32_t a1, uint32_t a2, uint32_t a3,
    uint32_t b0, uint32_t b1)
{
    asm volatile(
        "mma.sync.aligned.m16n8k8.row.col.f32.tf32.tf32.f32 "
        "{%0,%1,%2,%3},{%4,%5,%6,%7},{%8,%9},{%0,%1,%2,%3};"
        : "+f"(d0), "+f"(d1), "+f"(d2), "+f"(d3)
        : "r"(a0), "r"(a1), "r"(a2), "r"(a3), "r"(b0), "r"(b1));
}

// ---------------------------------------------------------------------------
// GEMM: Y[N, BNT] = X[N, 128] @ W[128, BNT]   (BNT = 128 or 64)
// Block tile 64x64, 128 threads (4 warps, warp tile 32x32), KC=32 chunks.
// SMEM holds pre-split {hi,lo} pairs.
// ---------------------------------------------------------------------------
template <int BNT>
__global__ __launch_bounds__(128, 4) void gemm_tc_kernel(
    const float* __restrict__ X, const float* __restrict__ W,
    float* __restrict__ Y, int N)
{
    constexpr int KC   = 32;
    constexpr int NK   = 128 / KC;     // 4 chunks
    constexpr int XSP2 = 36;           // Xs2 row stride in float2 (conflict-free)
    constexpr int WSP2 = 68;           // Ws2 row stride in float2 (conflict-free)

    __shared__ float2 Xs2[64][XSP2];   // [row][k] = {hi,lo}
    __shared__ float2 Ws2[KC][WSP2];   // [k][col] = {hi,lo}

    const int tid  = threadIdx.x;
    const int lane = tid & 31;
    const int warp = tid >> 5;
    const int row0 = blockIdx.x * 64;
    const int nb   = blockIdx.y * 64;

    const int qr = lane >> 2;   // 0..7
    const int qt = lane & 3;    // 0..3
    const int wm = (warp & 1) * 32;
    const int wn = (warp >> 1) * 32;

    const float4* X4 = (const float4*)X;
    const float4* W4 = (const float4*)W;

    float4 xr[4], wr[4];

    auto ldgX = [&](int ch) {
#pragma unroll
        for (int i = 0; i < 4; i++) {
            int idx = tid + i * 128;            // over 64*8 float4
            int r = idx >> 3, c4 = idx & 7;
            int gr = row0 + r;
            xr[i] = (gr < N) ? X4[gr * 32 + ch * 8 + c4]
                             : make_float4(0.f, 0.f, 0.f, 0.f);
        }
    };
    auto ldgW = [&](int ch) {
#pragma unroll
        for (int i = 0; i < 4; i++) {
            int idx = tid + i * 128;            // over 32*16 float4
            int kk = idx >> 4, cc = idx & 15;
            wr[i] = W4[(((ch * KC + kk) * BNT + nb) >> 2) + cc];
        }
    };
    auto stsX = [&]() {
#pragma unroll
        for (int i = 0; i < 4; i++) {
            int idx = tid + i * 128;
            int r = idx >> 3, c4 = idx & 7;
            Xs2[r][c4 * 4 + 0] = tf32_split2(xr[i].x);
            Xs2[r][c4 * 4 + 1] = tf32_split2(xr[i].y);
            Xs2[r][c4 * 4 + 2] = tf32_split2(xr[i].z);
            Xs2[r][c4 * 4 + 3] = tf32_split2(xr[i].w);
        }
    };
    auto stsW = [&]() {
#pragma unroll
        for (int i = 0; i < 4; i++) {
            int idx = tid + i * 128;
            int kk = idx >> 4, cc = idx & 15;
            Ws2[kk][cc * 4 + 0] = tf32_split2(wr[i].x);
            Ws2[kk][cc * 4 + 1] = tf32_split2(wr[i].y);
            Ws2[kk][cc * 4 + 2] = tf32_split2(wr[i].z);
            Ws2[kk][cc * 4 + 3] = tf32_split2(wr[i].w);
        }
    };

    float acc[2][4][4] = {};

    ldgX(0); ldgW(0);
    stsX(); stsW();
    __syncthreads();

#pragma unroll
    for (int ch = 0; ch < NK; ch++) {
        if (ch + 1 < NK) { ldgX(ch + 1); ldgW(ch + 1); }

#pragma unroll
        for (int ks = 0; ks < KC / 8; ks++) {
            const int kb = ks * 8 + qt;

            uint32_t ahi[2][4], alo[2][4];
#pragma unroll
            for (int mt = 0; mt < 2; mt++) {
                int r = wm + mt * 16 + qr;
                float2 p0 = Xs2[r][kb];
                float2 p1 = Xs2[r + 8][kb];
                float2 p2 = Xs2[r][kb + 4];
                float2 p3 = Xs2[r + 8][kb + 4];
                ahi[mt][0] = __float_as_uint(p0.x); alo[mt][0] = __float_as_uint(p0.y);
                ahi[mt][1] = __float_as_uint(p1.x); alo[mt][1] = __float_as_uint(p1.y);
                ahi[mt][2] = __float_as_uint(p2.x); alo[mt][2] = __float_as_uint(p2.y);
                ahi[mt][3] = __float_as_uint(p3.x); alo[mt][3] = __float_as_uint(p3.y);
            }
            uint32_t bhi[4][2], blo[4][2];
#pragma unroll
            for (int nt = 0; nt < 4; nt++) {
                int c = wn + nt * 8 + qr;
                float2 q0 = Ws2[ks * 8 + qt][c];
                float2 q1 = Ws2[ks * 8 + qt + 4][c];
                bhi[nt][0] = __float_as_uint(q0.x); blo[nt][0] = __float_as_uint(q0.y);
                bhi[nt][1] = __float_as_uint(q1.x); blo[nt][1] = __float_as_uint(q1.y);
            }
#pragma unroll
            for (int mt = 0; mt < 2; mt++)
#pragma unroll
                for (int nt = 0; nt < 4; nt++) {
                    float* d = acc[mt][nt];
                    mma_tf32(d[0], d[1], d[2], d[3],
                             ahi[mt][0], ahi[mt][1], ahi[mt][2], ahi[mt][3],
                             bhi[nt][0], bhi[nt][1]);
                    mma_tf32(d[0], d[1], d[2], d[3],
                             ahi[mt][0], ahi[mt][1], ahi[mt][2], ahi[mt][3],
                             blo[nt][0], blo[nt][1]);
                    mma_tf32(d[0], d[1], d[2], d[3],
                             alo[mt][0], alo[mt][1], alo[mt][2], alo[mt][3],
                             bhi[nt][0], bhi[nt][1]);
                }
        }

        if (ch + 1 < NK) {
            __syncthreads();
            stsX(); stsW();
            __syncthreads();
        }
    }

    // Epilogue
#pragma unroll
    for (int mt = 0; mt < 2; mt++) {
#pragma unroll
        for (int nt = 0; nt < 4; nt++) {
            int gc = nb + wn + nt * 8 + qt * 2;
            int r0g = row0 + wm + mt * 16 + qr;
            if (r0g < N)
                *(float2*)&Y[r0g * BNT + gc] =
                    make_float2(acc[mt][nt][0], acc[mt][nt][1]);
            int r1g = r0g + 8;
            if (r1g < N)
                *(float2*)&Y[r1g * BNT + gc] =
                    make_float2(acc[mt][nt][2], acc[mt][nt][3]);
        }
    }
}

// ---------------------------------------------------------------------------
// CSR build
// ---------------------------------------------------------------------------
__global__ __launch_bounds__(256) void hist_kernel(
    const int* __restrict__ dst, int* __restrict__ deg, int E)
{
    int e = blockIdx.x * blockDim.x + threadIdx.x;
    if (e < E) atomicAdd(&deg[__ldg(&dst[e])], 1);
}

__global__ __launch_bounds__(1024) void scan_kernel(
    const int* __restrict__ deg, int* __restrict__ indptr,
    int* __restrict__ cursor)
{
    __shared__ int sh[1024];
    const int CHUNK = (N_NODES + 1023) / 1024;
    int t = threadIdx.x;
    int begin = t * CHUNK;
    int end   = begin + CHUNK; if (end > N_NODES) end = N_NODES;

    int s = 0;
    for (int i = begin; i < end; i++) s += deg[i];
    sh[t] = s;
    __syncthreads();

    for (int off = 1; off < 1024; off <<= 1) {
        int v = sh[t];
        int a = (t >= off) ? sh[t - off] : 0;
        __syncthreads();
        sh[t] = v + a;
        __syncthreads();
    }

    int run = (t == 0) ? 0 : sh[t - 1];
    for (int i = begin; i < end; i++) {
        indptr[i] = run;
        cursor[i] = run;
        run += deg[i];
    }
}

__global__ __launch_bounds__(256) void place_kernel(
    const int* __restrict__ src, const int* __restrict__ dst,
    const float* __restrict__ ew, int* __restrict__ cursor,
    float2* __restrict__ edges, int E)
{
    int e = blockIdx.x * blockDim.x + threadIdx.x;
    if (e >= E) return;
    int d = __ldg(&dst[e]);
    int p = atomicAdd(&cursor[d], 1);
    edges[p] = make_float2(__int_as_float(__ldg(&src[e])), __ldg(&ew[e]));
}

// ---------------------------------------------------------------------------
// Gather-aggregate, D=128: one warp per dst node, lane = float4 chunk.
// Unroll-4 with independent accumulators for MLP.
// MODE 0: val=acc+b; out0=val; out1=val+relu(val)    (layer 0)
// MODE 1: val=acc+b; out0=Bres+relu(val)             (layer 1)
// ---------------------------------------------------------------------------
__device__ __forceinline__ void fma4(float4& a, const float4 v, const float w) {
    a.x = fmaf(v.x, w, a.x); a.y = fmaf(v.y, w, a.y);
    a.z = fmaf(v.z, w, a.z); a.w = fmaf(v.w, w, a.w);
}

template <int MODE>
__global__ __launch_bounds__(256) void gather128_kernel(
    const float* __restrict__ H, const float2* __restrict__ edges,
    const int* __restrict__ indptr, const int* __restrict__ deg,
    const float* __restrict__ bias, const float* __restrict__ Bres,
    float* __restrict__ out0, float* __restrict__ out1)
{
    int warp = (blockIdx.x * 256 + threadIdx.x) >> 5;
    int lane = threadIdx.x & 31;
    if (warp >= N_NODES) return;
    int node = warp;

    int start = __ldg(&indptr[node]);
    int cnt   = __ldg(&deg[node]);

    float4 a0 = make_float4(0.f, 0.f, 0.f, 0.f);
    float4 a1 = a0, a2 = a0, a3 = a0;
    const float4* H4 = (const float4*)H;

    int j = 0;
    for (; j + 3 < cnt; j += 4) {
        float2 e0 = __ldg(&edges[start + j]);
        float2 e1 = __ldg(&edges[start + j + 1]);
        float2 e2 = __ldg(&edges[start + j + 2]);
        float2 e3 = __ldg(&edges[start + j + 3]);
        float4 v0 = __ldg(&H4[(__float_as_int(e0.x) << 5) + lane]);
        float4 v1 = __ldg(&H4[(__float_as_int(e1.x) << 5) + lane]);
        float4 v2 = __ldg(&H4[(__float_as_int(e2.x) << 5) + lane]);
        float4 v3 = __ldg(&H4[(__float_as_int(e3.x) << 5) + lane]);
        fma4(a0, v0, e0.y); fma4(a1, v1, e1.y);
        fma4(a2, v2, e2.y); fma4(a3, v3, e3.y);
    }
    for (; j < cnt; j++) {
        float2 e0 = __ldg(&edges[start + j]);
        float4 v0 = __ldg(&H4[(__float_as_int(e0.x) << 5) + lane]);
        fma4(a0, v0, e0.y);
    }
    float4 acc;
    acc.x = (a0.x + a1.x) + (a2.x + a3.x);
    acc.y = (a0.y + a1.y) + (a2.y + a3.y);
    acc.z = (a0.z + a1.z) + (a2.z + a3.z);
    acc.w = (a0.w + a1.w) + (a2.w + a3.w);

    float4 bb = ((const float4*)bias)[lane];
    float4 val = make_float4(acc.x + bb.x, acc.y + bb.y,
                             acc.z + bb.z, acc.w + bb.w);
    int idx = (node << 5) + lane;

    if (MODE == 0) {
        ((float4*)out0)[idx] = val;
        float4 c;
        c.x = val.x + fmaxf(val.x, 0.f); c.y = val.y + fmaxf(val.y, 0.f);
        c.z = val.z + fmaxf(val.z, 0.f); c.w = val.w + fmaxf(val.w, 0.f);
        ((float4*)out1)[idx] = c;
    } else {
        float4 b = __ldg(&((const float4*)Bres)[idx]);
        float4 c;
        c.x = b.x + fmaxf(val.x, 0.f); c.y = b.y + fmaxf(val.y, 0.f);
        c.z = b.z + fmaxf(val.z, 0.f); c.w = b.w + fmaxf(val.w, 0.f);
        ((float4*)out0)[idx] = c;
    }
}

// D=64: half-warp per node.
__global__ __launch_bounds__(256) void gather64_kernel(
    const float* __restrict__ H, const float2* __restrict__ edges,
    const int* __restrict__ indptr, const int* __restrict__ deg,
    const float* __restrict__ bias, float* __restrict__ out)
{
    int half = (blockIdx.x * 256 + threadIdx.x) >> 4;
    int lane = threadIdx.x & 15;
    if (half >= N_NODES) return;
    int node = half;

    int start = __ldg(&indptr[node]);
    int cnt   = __ldg(&deg[node]);

    float4 a0 = make_float4(0.f, 0.f, 0.f, 0.f);
    float4 a1 = a0, a2 = a0, a3 = a0;
    const float4* H4 = (const float4*)H;

    int j = 0;
    for (; j + 3 < cnt; j += 4) {
        float2 e0 = __ldg(&edges[start + j]);
        float2 e1 = __ldg(&edges[start + j + 1]);
        float2 e2 = __ldg(&edges[start + j + 2]);
        float2 e3 = __ldg(&edges[start + j + 3]);
        float4 v0 = __ldg(&H4[(__float_as_int(e0.x) << 4) + lane]);
        float4 v1 = __ldg(&H4[(__float_as_int(e1.x) << 4) + lane]);
        float4 v2 = __ldg(&H4[(__float_as_int(e2.x) << 4) + lane]);
        float4 v3 = __ldg(&H4[(__float_as_int(e3.x) << 4) + lane]);
        fma4(a0, v0, e0.y); fma4(a1, v1, e1.y);
        fma4(a2, v2, e2.y); fma4(a3, v3, e3.y);
    }
    for (; j < cnt; j++) {
        float2 e0 = __ldg(&edges[start + j]);
        float4 v0 = __ldg(&H4[(__float_as_int(e0.x) << 4) + lane]);
        fma4(a0, v0, e0.y);
    }
    float4 acc;
    acc.x = (a0.x + a1.x) + (a2.x + a3.x);
    acc.y = (a0.y + a1.y) + (a2.y + a3.y);
    acc.z = (a0.z + a1.z) + (a2.z + a3.z);
    acc.w = (a0.w + a1.w) + (a2.w + a3.w);

    float4 bb = ((const float4*)bias)[lane];
    ((float4*)out)[(node << 4) + lane] =
        make_float4(acc.x + bb.x, acc.y + bb.y, acc.z + bb.z, acc.w + bb.w);
}

// ---------------------------------------------------------------------------

extern "C" void kernel_launch(void* const* d_in, const int* in_sizes, int n_in,
                              void* d_out, int out_size)
{
    const float* x  = (const float*)d_in[0];
    const int*   ei = (const int*)d_in[1];
    const float* ea = (const float*)d_in[2];
    const float* W1 = (const float*)d_in[3];
    const float* b1 = (const float*)d_in[4];
    const float* W2 = (const float*)d_in[5];
    const float* b2 = (const float*)d_in[6];
    const float* W3 = (const float*)d_in[7];
    const float* b3 = (const float*)d_in[8];
    float* out = (float*)d_out;

    const int N = N_NODES;
    const int E = N_EDGES;
    const int* src = ei;
    const int* dst = ei + E;

    float *A, *B, *C;
    int *deg, *indptr, *cursor;
    float2* edges;
    cudaGetSymbolAddress((void**)&A, g_bufA);
    cudaGetSymbolAddress((void**)&B, g_bufB);
    cudaGetSymbolAddress((void**)&C, g_bufC);
    cudaGetSymbolAddress((void**)&deg, g_deg);
    cudaGetSymbolAddress((void**)&indptr, g_indptr);
    cudaGetSymbolAddress((void**)&cursor, g_cursor);
    cudaGetSymbolAddress((void**)&edges, g_edges);

    const int e_blocks    = (E + 255) / 256;
    const int g128_blocks = (N * 32 + 255) / 256;
    const int g64_blocks  = (N * 16 + 255) / 256;
    const int mrows       = (N + 63) / 64;          // 782

    dim3 grid128(mrows, 2);   // BNT=128
    dim3 grid64(mrows, 1);    // BNT=64

    // --- CSR build (reused by all 3 layers) ---
    cudaMemsetAsync(deg, 0, N * sizeof(int));
    hist_kernel<<<e_blocks, 256>>>(dst, deg, E);
    scan_kernel<<<1, 1024>>>(deg, indptr, cursor);
    place_kernel<<<e_blocks, 256>>>(src, dst, ea, cursor, edges, E);

    // --- Layer 0: B = x1 = agg(x@W1)+b1 ; C = x1 + relu(x1) ---
    gemm_tc_kernel<128><<<grid128, 128>>>(x, W1, A, N);
    gather128_kernel<0><<<g128_blocks, 256>>>(A, edges, indptr, deg, b1, nullptr, B, C);

    // --- Layer 1: C = x1 + relu(agg(C@W2)+b2) ---
    gemm_tc_kernel<128><<<grid128, 128>>>(C, W2, A, N);
    gather128_kernel<1><<<g128_blocks, 256>>>(A, edges, indptr, deg, b2, B, C, nullptr);

    // --- Layer 2: out = agg(C@W3)+b3 ---
    gemm_tc_kernel<64><<<grid64, 128>>>(C, W3, A, N);
    gather64_kernel<<<g64_blocks, 256>>>(A, edges, indptr, deg, b3, out);
}

// round 6
// speedup vs baseline: 1.1138x; 1.1138x over previous
#include <cuda_runtime.h>
#include <cuda_bf16.h>
#include <cstdint>

// ---------------------------------------------------------------------------
// QGCN forward on GB300 — CSR gather + split-TF32 tensor-core GEMM.
//   GEMM: Y = X @ W via mma.sync.m16n8k8.tf32, 3-pass hi/lo split (~fp32 acc).
//   hi/lo pre-split at SMEM staging into SEPARATE scalar arrays (R4 geometry,
//   conflict-free fragment loads).
// ---------------------------------------------------------------------------

#define N_NODES 50000
#define N_EDGES 800000

__device__ float  g_bufA[N_NODES * 128];
__device__ float  g_bufB[N_NODES * 128];
__device__ float  g_bufC[N_NODES * 128];
__device__ int    g_deg[N_NODES];
__device__ int    g_indptr[N_NODES];
__device__ int    g_cursor[N_NODES];
__device__ float2 g_edges[N_EDGES];   // {src (bit-cast int), weight}

// ---------------------------------------------------------------------------
// TF32 helpers
// ---------------------------------------------------------------------------
__device__ __forceinline__ uint32_t f2tf32(float x) {
    uint32_t r;
    asm("cvt.rna.tf32.f32 %0, %1;" : "=r"(r) : "f"(x));
    return r;
}
__device__ __forceinline__ void mma_tf32(
    float& d0, float& d1, float& d2, float& d3,
    uint32_t a0, uint32_t a1, uint32_t a2, uint32_t a3,
    uint32_t b0, uint32_t b1)
{
    asm volatile(
        "mma.sync.aligned.m16n8k8.row.col.f32.tf32.tf32.f32 "
        "{%0,%1,%2,%3},{%4,%5,%6,%7},{%8,%9},{%0,%1,%2,%3};"
        : "+f"(d0), "+f"(d1), "+f"(d2), "+f"(d3)
        : "r"(a0), "r"(a1), "r"(a2), "r"(a3), "r"(b0), "r"(b1));
}

// ---------------------------------------------------------------------------
// GEMM: Y[N, BNT] = X[N, 128] @ W[128, BNT]   (BNT = 128 or 64)
// Block tile 64x64, 128 threads (4 warps, warp tile 32x32), KC=32 chunks.
// SMEM: separate hi/lo scalar arrays, R4 conflict-free strides.
// ---------------------------------------------------------------------------
template <int BNT>
__global__ __launch_bounds__(128, 4) void gemm_tc_kernel(
    const float* __restrict__ X, const float* __restrict__ W,
    float* __restrict__ Y, int N)
{
    constexpr int KC  = 32;
    constexpr int NK  = 128 / KC;      // 4 chunks
    constexpr int XSP = 36;            // row stride (floats) — conflict-free
    constexpr int WSP = 72;            // row stride (floats) — conflict-free

    __shared__ float Xh[64][XSP], Xl[64][XSP];
    __shared__ float Wh[KC][WSP], Wl[KC][WSP];

    const int tid  = threadIdx.x;
    const int lane = tid & 31;
    const int warp = tid >> 5;
    const int row0 = blockIdx.x * 64;
    const int nb   = blockIdx.y * 64;

    const int qr = lane >> 2;   // 0..7
    const int qt = lane & 3;    // 0..3
    const int wm = (warp & 1) * 32;
    const int wn = (warp >> 1) * 32;

    const float4* X4 = (const float4*)X;
    const float4* W4 = (const float4*)W;

    float4 xr[4], wr[4];

    auto ldgX = [&](int ch) {
#pragma unroll
        for (int i = 0; i < 4; i++) {
            int idx = tid + i * 128;            // over 64*8 float4
            int r = idx >> 3, c4 = idx & 7;
            int gr = row0 + r;
            xr[i] = (gr < N) ? X4[gr * 32 + ch * 8 + c4]
                             : make_float4(0.f, 0.f, 0.f, 0.f);
        }
    };
    auto ldgW = [&](int ch) {
#pragma unroll
        for (int i = 0; i < 4; i++) {
            int idx = tid + i * 128;            // over 32*16 float4
            int kk = idx >> 4, cc = idx & 15;
            wr[i] = W4[(((ch * KC + kk) * BNT + nb) >> 2) + cc];
        }
    };
    auto splitStore = [](float v, float* ph, float* pl) {
        uint32_t hi = f2tf32(v);
        *ph = __uint_as_float(hi);
        *pl = __uint_as_float(f2tf32(v - __uint_as_float(hi)));
    };
    auto stsX = [&]() {
#pragma unroll
        for (int i = 0; i < 4; i++) {
            int idx = tid + i * 128;
            int r = idx >> 3, c4 = idx & 7;
            splitStore(xr[i].x, &Xh[r][c4 * 4 + 0], &Xl[r][c4 * 4 + 0]);
            splitStore(xr[i].y, &Xh[r][c4 * 4 + 1], &Xl[r][c4 * 4 + 1]);
            splitStore(xr[i].z, &Xh[r][c4 * 4 + 2], &Xl[r][c4 * 4 + 2]);
            splitStore(xr[i].w, &Xh[r][c4 * 4 + 3], &Xl[r][c4 * 4 + 3]);
        }
    };
    auto stsW = [&]() {
#pragma unroll
        for (int i = 0; i < 4; i++) {
            int idx = tid + i * 128;
            int kk = idx >> 4, cc = idx & 15;
            splitStore(wr[i].x, &Wh[kk][cc * 4 + 0], &Wl[kk][cc * 4 + 0]);
            splitStore(wr[i].y, &Wh[kk][cc * 4 + 1], &Wl[kk][cc * 4 + 1]);
            splitStore(wr[i].z, &Wh[kk][cc * 4 + 2], &Wl[kk][cc * 4 + 2]);
            splitStore(wr[i].w, &Wh[kk][cc * 4 + 3], &Wl[kk][cc * 4 + 3]);
        }
    };

    float acc[2][4][4] = {};

    ldgX(0); ldgW(0);
    stsX(); stsW();
    __syncthreads();

#pragma unroll
    for (int ch = 0; ch < NK; ch++) {
        if (ch + 1 < NK) { ldgX(ch + 1); ldgW(ch + 1); }

#pragma unroll
        for (int ks = 0; ks < KC / 8; ks++) {
            const int kb = ks * 8 + qt;

            uint32_t ahi[2][4], alo[2][4];
#pragma unroll
            for (int mt = 0; mt < 2; mt++) {
                int r = wm + mt * 16 + qr;
                ahi[mt][0] = __float_as_uint(Xh[r][kb]);
                ahi[mt][1] = __float_as_uint(Xh[r + 8][kb]);
                ahi[mt][2] = __float_as_uint(Xh[r][kb + 4]);
                ahi[mt][3] = __float_as_uint(Xh[r + 8][kb + 4]);
                alo[mt][0] = __float_as_uint(Xl[r][kb]);
                alo[mt][1] = __float_as_uint(Xl[r + 8][kb]);
                alo[mt][2] = __float_as_uint(Xl[r][kb + 4]);
                alo[mt][3] = __float_as_uint(Xl[r + 8][kb + 4]);
            }
            uint32_t bhi[4][2], blo[4][2];
#pragma unroll
            for (int nt = 0; nt < 4; nt++) {
                int c = wn + nt * 8 + qr;
                bhi[nt][0] = __float_as_uint(Wh[ks * 8 + qt][c]);
                bhi[nt][1] = __float_as_uint(Wh[ks * 8 + qt + 4][c]);
                blo[nt][0] = __float_as_uint(Wl[ks * 8 + qt][c]);
                blo[nt][1] = __float_as_uint(Wl[ks * 8 + qt + 4][c]);
            }
#pragma unroll
            for (int mt = 0; mt < 2; mt++)
#pragma unroll
                for (int nt = 0; nt < 4; nt++) {
                    float* d = acc[mt][nt];
                    mma_tf32(d[0], d[1], d[2], d[3],
                             ahi[mt][0], ahi[mt][1], ahi[mt][2], ahi[mt][3],
                             bhi[nt][0], bhi[nt][1]);
                    mma_tf32(d[0], d[1], d[2], d[3],
                             ahi[mt][0], ahi[mt][1], ahi[mt][2], ahi[mt][3],
                             blo[nt][0], blo[nt][1]);
                    mma_tf32(d[0], d[1], d[2], d[3],
                             alo[mt][0], alo[mt][1], alo[mt][2], alo[mt][3],
                             bhi[nt][0], bhi[nt][1]);
                }
        }

        if (ch + 1 < NK) {
            __syncthreads();
            stsX(); stsW();
            __syncthreads();
        }
    }

    // Epilogue
#pragma unroll
    for (int mt = 0; mt < 2; mt++) {
#pragma unroll
        for (int nt = 0; nt < 4; nt++) {
            int gc = nb + wn + nt * 8 + qt * 2;
            int r0g = row0 + wm + mt * 16 + qr;
            if (r0g < N)
                *(float2*)&Y[r0g * BNT + gc] =
                    make_float2(acc[mt][nt][0], acc[mt][nt][1]);
            int r1g = r0g + 8;
            if (r1g < N)
                *(float2*)&Y[r1g * BNT + gc] =
                    make_float2(acc[mt][nt][2], acc[mt][nt][3]);
        }
    }
}

// ---------------------------------------------------------------------------
// CSR build
// ---------------------------------------------------------------------------
__global__ __launch_bounds__(256) void hist_kernel(
    const int* __restrict__ dst, int* __restrict__ deg, int E)
{
    int e = blockIdx.x * blockDim.x + threadIdx.x;
    if (e < E) atomicAdd(&deg[__ldg(&dst[e])], 1);
}

__global__ __launch_bounds__(1024) void scan_kernel(
    const int* __restrict__ deg, int* __restrict__ indptr,
    int* __restrict__ cursor)
{
    __shared__ int sh[1024];
    const int CHUNK = (N_NODES + 1023) / 1024;
    int t = threadIdx.x;
    int begin = t * CHUNK;
    int end   = begin + CHUNK; if (end > N_NODES) end = N_NODES;

    int s = 0;
    for (int i = begin; i < end; i++) s += deg[i];
    sh[t] = s;
    __syncthreads();

    for (int off = 1; off < 1024; off <<= 1) {
        int v = sh[t];
        int a = (t >= off) ? sh[t - off] : 0;
        __syncthreads();
        sh[t] = v + a;
        __syncthreads();
    }

    int run = (t == 0) ? 0 : sh[t - 1];
    for (int i = begin; i < end; i++) {
        indptr[i] = run;
        cursor[i] = run;
        run += deg[i];
    }
}

__global__ __launch_bounds__(256) void place_kernel(
    const int* __restrict__ src, const int* __restrict__ dst,
    const float* __restrict__ ew, int* __restrict__ cursor,
    float2* __restrict__ edges, int E)
{
    int e = blockIdx.x * blockDim.x + threadIdx.x;
    if (e >= E) return;
    int d = __ldg(&dst[e]);
    int p = atomicAdd(&cursor[d], 1);
    edges[p] = make_float2(__int_as_float(__ldg(&src[e])), __ldg(&ew[e]));
}

// ---------------------------------------------------------------------------
// Gather-aggregate, D=128: one warp per dst node, lane = float4 chunk.
// (R4 unroll-2 form — measured best.)
// MODE 0: val=acc+b; out0=val; out1=val+relu(val)    (layer 0)
// MODE 1: val=acc+b; out0=Bres+relu(val)             (layer 1)
// ---------------------------------------------------------------------------
template <int MODE>
__global__ __launch_bounds__(256) void gather128_kernel(
    const float* __restrict__ H, const float2* __restrict__ edges,
    const int* __restrict__ indptr, const int* __restrict__ deg,
    const float* __restrict__ bias, const float* __restrict__ Bres,
    float* __restrict__ out0, float* __restrict__ out1)
{
    int warp = (blockIdx.x * 256 + threadIdx.x) >> 5;
    int lane = threadIdx.x & 31;
    if (warp >= N_NODES) return;
    int node = warp;

    int start = __ldg(&indptr[node]);
    int cnt   = __ldg(&deg[node]);

    float4 acc = make_float4(0.f, 0.f, 0.f, 0.f);
    const float4* H4 = (const float4*)H;

    int j = 0;
    for (; j + 1 < cnt; j += 2) {
        float2 e0 = __ldg(&edges[start + j]);
        float2 e1 = __ldg(&edges[start + j + 1]);
        float4 v0 = __ldg(&H4[(__float_as_int(e0.x) << 5) + lane]);
        float4 v1 = __ldg(&H4[(__float_as_int(e1.x) << 5) + lane]);
        acc.x = fmaf(v0.x, e0.y, acc.x); acc.y = fmaf(v0.y, e0.y, acc.y);
        acc.z = fmaf(v0.z, e0.y, acc.z); acc.w = fmaf(v0.w, e0.y, acc.w);
        acc.x = fmaf(v1.x, e1.y, acc.x); acc.y = fmaf(v1.y, e1.y, acc.y);
        acc.z = fmaf(v1.z, e1.y, acc.z); acc.w = fmaf(v1.w, e1.y, acc.w);
    }
    if (j < cnt) {
        float2 e0 = __ldg(&edges[start + j]);
        float4 v0 = __ldg(&H4[(__float_as_int(e0.x) << 5) + lane]);
        acc.x = fmaf(v0.x, e0.y, acc.x); acc.y = fmaf(v0.y, e0.y, acc.y);
        acc.z = fmaf(v0.z, e0.y, acc.z); acc.w = fmaf(v0.w, e0.y, acc.w);
    }

    float4 bb = ((const float4*)bias)[lane];
    float4 val = make_float4(acc.x + bb.x, acc.y + bb.y,
                             acc.z + bb.z, acc.w + bb.w);
    int idx = (node << 5) + lane;

    if (MODE == 0) {
        ((float4*)out0)[idx] = val;
        float4 c;
        c.x = val.x + fmaxf(val.x, 0.f); c.y = val.y + fmaxf(val.y, 0.f);
        c.z = val.z + fmaxf(val.z, 0.f); c.w = val.w + fmaxf(val.w, 0.f);
        ((float4*)out1)[idx] = c;
    } else {
        float4 b = __ldg(&((const float4*)Bres)[idx]);
        float4 c;
        c.x = b.x + fmaxf(val.x, 0.f); c.y = b.y + fmaxf(val.y, 0.f);
        c.z = b.z + fmaxf(val.z, 0.f); c.w = b.w + fmaxf(val.w, 0.f);
        ((float4*)out0)[idx] = c;
    }
}

// D=64: half-warp per node.
__global__ __launch_bounds__(256) void gather64_kernel(
    const float* __restrict__ H, const float2* __restrict__ edges,
    const int* __restrict__ indptr, const int* __restrict__ deg,
    const float* __restrict__ bias, float* __restrict__ out)
{
    int half = (blockIdx.x * 256 + threadIdx.x) >> 4;
    int lane = threadIdx.x & 15;
    if (half >= N_NODES) return;
    int node = half;

    int start = __ldg(&indptr[node]);
    int cnt   = __ldg(&deg[node]);

    float4 acc = make_float4(0.f, 0.f, 0.f, 0.f);
    const float4* H4 = (const float4*)H;

    int j = 0;
    for (; j + 1 < cnt; j += 2) {
        float2 e0 = __ldg(&edges[start + j]);
        float2 e1 = __ldg(&edges[start + j + 1]);
        float4 v0 = __ldg(&H4[(__float_as_int(e0.x) << 4) + lane]);
        float4 v1 = __ldg(&H4[(__float_as_int(e1.x) << 4) + lane]);
        acc.x = fmaf(v0.x, e0.y, acc.x); acc.y = fmaf(v0.y, e0.y, acc.y);
        acc.z = fmaf(v0.z, e0.y, acc.z); acc.w = fmaf(v0.w, e0.y, acc.w);
        acc.x = fmaf(v1.x, e1.y, acc.x); acc.y = fmaf(v1.y, e1.y, acc.y);
        acc.z = fmaf(v1.z, e1.y, acc.z); acc.w = fmaf(v1.w, e1.y, acc.w);
    }
    if (j < cnt) {
        float2 e0 = __ldg(&edges[start + j]);
        float4 v0 = __ldg(&H4[(__float_as_int(e0.x) << 4) + lane]);
        acc.x = fmaf(v0.x, e0.y, acc.x); acc.y = fmaf(v0.y, e0.y, acc.y);
        acc.z = fmaf(v0.z, e0.y, acc.z); acc.w = fmaf(v0.w, e0.y, acc.w);
    }

    float4 bb = ((const float4*)bias)[lane];
    ((float4*)out)[(node << 4) + lane] =
        make_float4(acc.x + bb.x, acc.y + bb.y, acc.z + bb.z, acc.w + bb.w);
}

// ---------------------------------------------------------------------------

extern "C" void kernel_launch(void* const* d_in, const int* in_sizes, int n_in,
                              void* d_out, int out_size)
{
    const float* x  = (const float*)d_in[0];
    const int*   ei = (const int*)d_in[1];
    const float* ea = (const float*)d_in[2];
    const float* W1 = (const float*)d_in[3];
    const float* b1 = (const float*)d_in[4];
    const float* W2 = (const float*)d_in[5];
    const float* b2 = (const float*)d_in[6];
    const float* W3 = (const float*)d_in[7];
    const float* b3 = (const float*)d_in[8];
    float* out = (float*)d_out;

    const int N = N_NODES;
    const int E = N_EDGES;
    const int* src = ei;
    const int* dst = ei + E;

    float *A, *B, *C;
    int *deg, *indptr, *cursor;
    float2* edges;
    cudaGetSymbolAddress((void**)&A, g_bufA);
    cudaGetSymbolAddress((void**)&B, g_bufB);
    cudaGetSymbolAddress((void**)&C, g_bufC);
    cudaGetSymbolAddress((void**)&deg, g_deg);
    cudaGetSymbolAddress((void**)&indptr, g_indptr);
    cudaGetSymbolAddress((void**)&cursor, g_cursor);
    cudaGetSymbolAddress((void**)&edges, g_edges);

    const int e_blocks    = (E + 255) / 256;
    const int g128_blocks = (N * 32 + 255) / 256;
    const int g64_blocks  = (N * 16 + 255) / 256;
    const int mrows       = (N + 63) / 64;          // 782

    dim3 grid128(mrows, 2);   // BNT=128
    dim3 grid64(mrows, 1);    // BNT=64

    // --- CSR build (reused by all 3 layers) ---
    cudaMemsetAsync(deg, 0, N * sizeof(int));
    hist_kernel<<<e_blocks, 256>>>(dst, deg, E);
    scan_kernel<<<1, 1024>>>(deg, indptr, cursor);
    place_kernel<<<e_blocks, 256>>>(src, dst, ea, cursor, edges, E);

    // --- Layer 0: B = x1 = agg(x@W1)+b1 ; C = x1 + relu(x1) ---
    gemm_tc_kernel<128><<<grid128, 128>>>(x, W1, A, N);
    gather128_kernel<0><<<g128_blocks, 256>>>(A, edges, indptr, deg, b1, nullptr, B, C);

    // --- Layer 1: C = x1 + relu(agg(C@W2)+b2) ---
    gemm_tc_kernel<128><<<grid128, 128>>>(C, W2, A, N);
    gather128_kernel<1><<<g128_blocks, 256>>>(A, edges, indptr, deg, b2, B, C, nullptr);

    // --- Layer 2: out = agg(C@W3)+b3 ---
    gemm_tc_kernel<64><<<grid64, 128>>>(C, W3, A, N);
    gather64_kernel<<<g64_blocks, 256>>>(A, edges, indptr, deg, b3, out);
}

// round 7
// speedup vs baseline: 1.3258x; 1.1903x over previous
#include <cuda_runtime.h>
#include <cuda_bf16.h>
#include <cstdint>

// ---------------------------------------------------------------------------
// QGCN forward on GB300 — CSR gather + split-BF16 tensor-core GEMM.
//   GEMM: Y = X @ W via mma.sync.m16n8k16.bf16, 3-pass hi/lo split.
//   SMEM holds packed bf16x2 (k-pairs), split done once at staging.
// ---------------------------------------------------------------------------

#define N_NODES 50000
#define N_EDGES 800000

__device__ float  g_bufA[N_NODES * 128];
__device__ float  g_bufB[N_NODES * 128];
__device__ float  g_bufC[N_NODES * 128];
__device__ int    g_deg[N_NODES];
__device__ int    g_indptr[N_NODES];
__device__ int    g_cursor[N_NODES];
__device__ float2 g_edges[N_EDGES];   // {src (bit-cast int), weight}

// ---------------------------------------------------------------------------
// BF16 helpers
// ---------------------------------------------------------------------------
__device__ __forceinline__ uint32_t pack_bf16x2(__nv_bfloat16 lo16, __nv_bfloat16 hi16) {
    __nv_bfloat162 t;
    t.x = lo16;   // lower k index -> low 16 bits
    t.y = hi16;
    return *reinterpret_cast<uint32_t*>(&t);
}
// split a,b (consecutive k) into packed hi word and packed lo word
__device__ __forceinline__ void split_pair(float a, float b,
                                           uint32_t& wh, uint32_t& wl) {
    __nv_bfloat16 ah = __float2bfloat16_rn(a);
    __nv_bfloat16 bh = __float2bfloat16_rn(b);
    __nv_bfloat16 al = __float2bfloat16_rn(a - __bfloat162float(ah));
    __nv_bfloat16 bl = __float2bfloat16_rn(b - __bfloat162float(bh));
    wh = pack_bf16x2(ah, bh);
    wl = pack_bf16x2(al, bl);
}
__device__ __forceinline__ void mma_bf16(
    float& d0, float& d1, float& d2, float& d3,
    uint32_t a0, uint32_t a1, uint32_t a2, uint32_t a3,
    uint32_t b0, uint32_t b1)
{
    asm volatile(
        "mma.sync.aligned.m16n8k16.row.col.f32.bf16.bf16.f32 "
        "{%0,%1,%2,%3},{%4,%5,%6,%7},{%8,%9},{%0,%1,%2,%3};"
        : "+f"(d0), "+f"(d1), "+f"(d2), "+f"(d3)
        : "r"(a0), "r"(a1), "r"(a2), "r"(a3), "r"(b0), "r"(b1));
}

// ---------------------------------------------------------------------------
// GEMM: Y[N, BNT] = X[N, 128] @ W[128, BNT]   (BNT = 128 or 64)
// Block tile 64x64, 128 threads (4 warps, warp tile 32x32), KC=32 chunks.
// SMEM: packed bf16x2 hi/lo arrays; word strides 20 / 72 (bank-conflict-free
// fragment loads, same index pattern as the tf32 version).
// ---------------------------------------------------------------------------
template <int BNT>
__global__ __launch_bounds__(128, 4) void gemm_tc_kernel(
    const float* __restrict__ X, const float* __restrict__ W,
    float* __restrict__ Y, int N)
{
    constexpr int KC   = 32;
    constexpr int NK   = 128 / KC;     // 4 chunks
    constexpr int XSPW = 20;           // X word stride (16 words + pad)
    constexpr int WSPW = 72;           // W word stride (64 words + pad)

    __shared__ uint32_t Xh[64][XSPW], Xl[64][XSPW];
    __shared__ uint32_t Wh[16][WSPW], Wl[16][WSPW];

    const int tid  = threadIdx.x;
    const int lane = tid & 31;
    const int warp = tid >> 5;
    const int row0 = blockIdx.x * 64;
    const int nb   = blockIdx.y * 64;

    const int qr = lane >> 2;   // 0..7
    const int qt = lane & 3;    // 0..3
    const int wm = (warp & 1) * 32;
    const int wn = (warp >> 1) * 32;

    const float4* X4 = (const float4*)X;
    const float4* W4 = (const float4*)W;

    float4 xr[4];        // X: 64 rows x 8 float4 per chunk
    float4 wrA[2], wrB[2];  // W: 16 k-pairs x 16 float4 pairs per chunk

    auto ldgX = [&](int ch) {
#pragma unroll
        for (int i = 0; i < 4; i++) {
            int idx = tid + i * 128;            // over 64*8 float4
            int r = idx >> 3, c4 = idx & 7;
            int gr = row0 + r;
            xr[i] = (gr < N) ? X4[gr * 32 + ch * 8 + c4]
                             : make_float4(0.f, 0.f, 0.f, 0.f);
        }
    };
    auto ldgW = [&](int ch) {
#pragma unroll
        for (int i = 0; i < 2; i++) {
            int idx = tid + i * 128;            // over 16 kp * 16 col4
            int kp = idx >> 4, cc = idx & 15;
            wrA[i] = W4[(((ch * KC + 2 * kp)     * BNT + nb) >> 2) + cc];
            wrB[i] = W4[(((ch * KC + 2 * kp + 1) * BNT + nb) >> 2) + cc];
        }
    };
    auto stsX = [&]() {
#pragma unroll
        for (int i = 0; i < 4; i++) {
            int idx = tid + i * 128;
            int r = idx >> 3, c4 = idx & 7;
            uint32_t h0, l0, h1, l1;
            split_pair(xr[i].x, xr[i].y, h0, l0);
            split_pair(xr[i].z, xr[i].w, h1, l1);
            Xh[r][c4 * 2 + 0] = h0;  Xl[r][c4 * 2 + 0] = l0;
            Xh[r][c4 * 2 + 1] = h1;  Xl[r][c4 * 2 + 1] = l1;
        }
    };
    auto stsW = [&]() {
#pragma unroll
        for (int i = 0; i < 2; i++) {
            int idx = tid + i * 128;
            int kp = idx >> 4, cc = idx & 15;
            const float* a = (const float*)&wrA[i];
            const float* b = (const float*)&wrB[i];
#pragma unroll
            for (int j = 0; j < 4; j++) {
                uint32_t wh, wl;
                split_pair(a[j], b[j], wh, wl);   // (k even, k odd)
                Wh[kp][cc * 4 + j] = wh;
                Wl[kp][cc * 4 + j] = wl;
            }
        }
    };

    float acc[2][4][4] = {};

    ldgX(0); ldgW(0);
    stsX(); stsW();
    __syncthreads();

#pragma unroll
    for (int ch = 0; ch < NK; ch++) {
        if (ch + 1 < NK) { ldgX(ch + 1); ldgW(ch + 1); }

#pragma unroll
        for (int ks = 0; ks < 2; ks++) {          // two k16 steps per chunk
            const int kw = ks * 8 + qt;           // word index within chunk

            uint32_t ahi[2][4], alo[2][4];
#pragma unroll
            for (int mt = 0; mt < 2; mt++) {
                int r = wm + mt * 16 + qr;
                ahi[mt][0] = Xh[r][kw];
                ahi[mt][1] = Xh[r + 8][kw];
                ahi[mt][2] = Xh[r][kw + 4];
                ahi[mt][3] = Xh[r + 8][kw + 4];
                alo[mt][0] = Xl[r][kw];
                alo[mt][1] = Xl[r + 8][kw];
                alo[mt][2] = Xl[r][kw + 4];
                alo[mt][3] = Xl[r + 8][kw + 4];
            }
            uint32_t bhi[4][2], blo[4][2];
#pragma unroll
            for (int nt = 0; nt < 4; nt++) {
                int c = wn + nt * 8 + qr;
                bhi[nt][0] = Wh[ks * 8 + qt][c];
                bhi[nt][1] = Wh[ks * 8 + qt + 4][c];
                blo[nt][0] = Wl[ks * 8 + qt][c];
                blo[nt][1] = Wl[ks * 8 + qt + 4][c];
            }
#pragma unroll
            for (int mt = 0; mt < 2; mt++)
#pragma unroll
                for (int nt = 0; nt < 4; nt++) {
                    float* d = acc[mt][nt];
                    mma_bf16(d[0], d[1], d[2], d[3],
                             ahi[mt][0], ahi[mt][1], ahi[mt][2], ahi[mt][3],
                             bhi[nt][0], bhi[nt][1]);
                    mma_bf16(d[0], d[1], d[2], d[3],
                             ahi[mt][0], ahi[mt][1], ahi[mt][2], ahi[mt][3],
                             blo[nt][0], blo[nt][1]);
                    mma_bf16(d[0], d[1], d[2], d[3],
                             alo[mt][0], alo[mt][1], alo[mt][2], alo[mt][3],
                             bhi[nt][0], bhi[nt][1]);
                }
        }

        if (ch + 1 < NK) {
            __syncthreads();
            stsX(); stsW();
            __syncthreads();
        }
    }

    // Epilogue
#pragma unroll
    for (int mt = 0; mt < 2; mt++) {
#pragma unroll
        for (int nt = 0; nt < 4; nt++) {
            int gc = nb + wn + nt * 8 + qt * 2;
            int r0g = row0 + wm + mt * 16 + qr;
            if (r0g < N)
                *(float2*)&Y[r0g * BNT + gc] =
                    make_float2(acc[mt][nt][0], acc[mt][nt][1]);
            int r1g = r0g + 8;
            if (r1g < N)
                *(float2*)&Y[r1g * BNT + gc] =
                    make_float2(acc[mt][nt][2], acc[mt][nt][3]);
        }
    }
}

// ---------------------------------------------------------------------------
// CSR build
// ---------------------------------------------------------------------------
__global__ __launch_bounds__(256) void hist_kernel(
    const int* __restrict__ dst, int* __restrict__ deg, int E)
{
    int e = blockIdx.x * blockDim.x + threadIdx.x;
    if (e < E) atomicAdd(&deg[__ldg(&dst[e])], 1);
}

__global__ __launch_bounds__(1024) void scan_kernel(
    const int* __restrict__ deg, int* __restrict__ indptr,
    int* __restrict__ cursor)
{
    __shared__ int sh[1024];
    const int CHUNK = (N_NODES + 1023) / 1024;
    int t = threadIdx.x;
    int begin = t * CHUNK;
    int end   = begin + CHUNK; if (end > N_NODES) end = N_NODES;

    int s = 0;
    for (int i = begin; i < end; i++) s += deg[i];
    sh[t] = s;
    __syncthreads();

    for (int off = 1; off < 1024; off <<= 1) {
        int v = sh[t];
        int a = (t >= off) ? sh[t - off] : 0;
        __syncthreads();
        sh[t] = v + a;
        __syncthreads();
    }

    int run = (t == 0) ? 0 : sh[t - 1];
    for (int i = begin; i < end; i++) {
        indptr[i] = run;
        cursor[i] = run;
        run += deg[i];
    }
}

__global__ __launch_bounds__(256) void place_kernel(
    const int* __restrict__ src, const int* __restrict__ dst,
    const float* __restrict__ ew, int* __restrict__ cursor,
    float2* __restrict__ edges, int E)
{
    int e = blockIdx.x * blockDim.x + threadIdx.x;
    if (e >= E) return;
    int d = __ldg(&dst[e]);
    int p = atomicAdd(&cursor[d], 1);
    edges[p] = make_float2(__int_as_float(__ldg(&src[e])), __ldg(&ew[e]));
}

// ---------------------------------------------------------------------------
// Gather-aggregate, D=128: one warp per dst node, lane = float4 chunk.
// (R4 unroll-2 form — measured best.)
// MODE 0: val=acc+b; out0=val; out1=val+relu(val)    (layer 0)
// MODE 1: val=acc+b; out0=Bres+relu(val)             (layer 1)
// ---------------------------------------------------------------------------
template <int MODE>
__global__ __launch_bounds__(256) void gather128_kernel(
    const float* __restrict__ H, const float2* __restrict__ edges,
    const int* __restrict__ indptr, const int* __restrict__ deg,
    const float* __restrict__ bias, const float* __restrict__ Bres,
    float* __restrict__ out0, float* __restrict__ out1)
{
    int warp = (blockIdx.x * 256 + threadIdx.x) >> 5;
    int lane = threadIdx.x & 31;
    if (warp >= N_NODES) return;
    int node = warp;

    int start = __ldg(&indptr[node]);
    int cnt   = __ldg(&deg[node]);

    float4 acc = make_float4(0.f, 0.f, 0.f, 0.f);
    const float4* H4 = (const float4*)H;

    int j = 0;
    for (; j + 1 < cnt; j += 2) {
        float2 e0 = __ldg(&edges[start + j]);
        float2 e1 = __ldg(&edges[start + j + 1]);
        float4 v0 = __ldg(&H4[(__float_as_int(e0.x) << 5) + lane]);
        float4 v1 = __ldg(&H4[(__float_as_int(e1.x) << 5) + lane]);
        acc.x = fmaf(v0.x, e0.y, acc.x); acc.y = fmaf(v0.y, e0.y, acc.y);
        acc.z = fmaf(v0.z, e0.y, acc.z); acc.w = fmaf(v0.w, e0.y, acc.w);
        acc.x = fmaf(v1.x, e1.y, acc.x); acc.y = fmaf(v1.y, e1.y, acc.y);
        acc.z = fmaf(v1.z, e1.y, acc.z); acc.w = fmaf(v1.w, e1.y, acc.w);
    }
    if (j < cnt) {
        float2 e0 = __ldg(&edges[start + j]);
        float4 v0 = __ldg(&H4[(__float_as_int(e0.x) << 5) + lane]);
        acc.x = fmaf(v0.x, e0.y, acc.x); acc.y = fmaf(v0.y, e0.y, acc.y);
        acc.z = fmaf(v0.z, e0.y, acc.z); acc.w = fmaf(v0.w, e0.y, acc.w);
    }

    float4 bb = ((const float4*)bias)[lane];
    float4 val = make_float4(acc.x + bb.x, acc.y + bb.y,
                             acc.z + bb.z, acc.w + bb.w);
    int idx = (node << 5) + lane;

    if (MODE == 0) {
        ((float4*)out0)[idx] = val;
        float4 c;
        c.x = val.x + fmaxf(val.x, 0.f); c.y = val.y + fmaxf(val.y, 0.f);
        c.z = val.z + fmaxf(val.z, 0.f); c.w = val.w + fmaxf(val.w, 0.f);
        ((float4*)out1)[idx] = c;
    } else {
        float4 b = __ldg(&((const float4*)Bres)[idx]);
        float4 c;
        c.x = b.x + fmaxf(val.x, 0.f); c.y = b.y + fmaxf(val.y, 0.f);
        c.z = b.z + fmaxf(val.z, 0.f); c.w = b.w + fmaxf(val.w, 0.f);
        ((float4*)out0)[idx] = c;
    }
}

// D=64: half-warp per node.
__global__ __launch_bounds__(256) void gather64_kernel(
    const float* __restrict__ H, const float2* __restrict__ edges,
    const int* __restrict__ indptr, const int* __restrict__ deg,
    const float* __restrict__ bias, float* __restrict__ out)
{
    int half = (blockIdx.x * 256 + threadIdx.x) >> 4;
    int lane = threadIdx.x & 15;
    if (half >= N_NODES) return;
    int node = half;

    int start = __ldg(&indptr[node]);
    int cnt   = __ldg(&deg[node]);

    float4 acc = make_float4(0.f, 0.f, 0.f, 0.f);
    const float4* H4 = (const float4*)H;

    int j = 0;
    for (; j + 1 < cnt; j += 2) {
        float2 e0 = __ldg(&edges[start + j]);
        float2 e1 = __ldg(&edges[start + j + 1]);
        float4 v0 = __ldg(&H4[(__float_as_int(e0.x) << 4) + lane]);
        float4 v1 = __ldg(&H4[(__float_as_int(e1.x) << 4) + lane]);
        acc.x = fmaf(v0.x, e0.y, acc.x); acc.y = fmaf(v0.y, e0.y, acc.y);
        acc.z = fmaf(v0.z, e0.y, acc.z); acc.w = fmaf(v0.w, e0.y, acc.w);
        acc.x = fmaf(v1.x, e1.y, acc.x); acc.y = fmaf(v1.y, e1.y, acc.y);
        acc.z = fmaf(v1.z, e1.y, acc.z); acc.w = fmaf(v1.w, e1.y, acc.w);
    }
    if (j < cnt) {
        float2 e0 = __ldg(&edges[start + j]);
        float4 v0 = __ldg(&H4[(__float_as_int(e0.x) << 4) + lane]);
        acc.x = fmaf(v0.x, e0.y, acc.x); acc.y = fmaf(v0.y, e0.y, acc.y);
        acc.z = fmaf(v0.z, e0.y, acc.z); acc.w = fmaf(v0.w, e0.y, acc.w);
    }

    float4 bb = ((const float4*)bias)[lane];
    ((float4*)out)[(node << 4) + lane] =
        make_float4(acc.x + bb.x, acc.y + bb.y, acc.z + bb.z, acc.w + bb.w);
}

// ---------------------------------------------------------------------------

extern "C" void kernel_launch(void* const* d_in, const int* in_sizes, int n_in,
                              void* d_out, int out_size)
{
    const float* x  = (const float*)d_in[0];
    const int*   ei = (const int*)d_in[1];
    const float* ea = (const float*)d_in[2];
    const float* W1 = (const float*)d_in[3];
    const float* b1 = (const float*)d_in[4];
    const float* W2 = (const float*)d_in[5];
    const float* b2 = (const float*)d_in[6];
    const float* W3 = (const float*)d_in[7];
    const float* b3 = (const float*)d_in[8];
    float* out = (float*)d_out;

    const int N = N_NODES;
    const int E = N_EDGES;
    const int* src = ei;
    const int* dst = ei + E;

    float *A, *B, *C;
    int *deg, *indptr, *cursor;
    float2* edges;
    cudaGetSymbolAddress((void**)&A, g_bufA);
    cudaGetSymbolAddress((void**)&B, g_bufB);
    cudaGetSymbolAddress((void**)&C, g_bufC);
    cudaGetSymbolAddress((void**)&deg, g_deg);
    cudaGetSymbolAddress((void**)&indptr, g_indptr);
    cudaGetSymbolAddress((void**)&cursor, g_cursor);
    cudaGetSymbolAddress((void**)&edges, g_edges);

    const int e_blocks    = (E + 255) / 256;
    const int g128_blocks = (N * 32 + 255) / 256;
    const int g64_blocks  = (N * 16 + 255) / 256;
    const int mrows       = (N + 63) / 64;          // 782

    dim3 grid128(mrows, 2);   // BNT=128
    dim3 grid64(mrows, 1);    // BNT=64

    // --- CSR build (reused by all 3 layers) ---
    cudaMemsetAsync(deg, 0, N * sizeof(int));
    hist_kernel<<<e_blocks, 256>>>(dst, deg, E);
    scan_kernel<<<1, 1024>>>(deg, indptr, cursor);
    place_kernel<<<e_blocks, 256>>>(src, dst, ea, cursor, edges, E);

    // --- Layer 0: B = x1 = agg(x@W1)+b1 ; C = x1 + relu(x1) ---
    gemm_tc_kernel<128><<<grid128, 128>>>(x, W1, A, N);
    gather128_kernel<0><<<g128_blocks, 256>>>(A, edges, indptr, deg, b1, nullptr, B, C);

    // --- Layer 1: C = x1 + relu(agg(C@W2)+b2) ---
    gemm_tc_kernel<128><<<grid128, 128>>>(C, W2, A, N);
    gather128_kernel<1><<<g128_blocks, 256>>>(A, edges, indptr, deg, b2, B, C, nullptr);

    // --- Layer 2: out = agg(C@W3)+b3 ---
    gemm_tc_kernel<64><<<grid64, 128>>>(C, W3, A, N);
    gather64_kernel<<<g64_blocks, 256>>>(A, edges, indptr, deg, b3, out);
}

// round 8
// speedup vs baseline: 1.3275x; 1.0013x over previous
#include <cuda_runtime.h>
#include <cuda_bf16.h>
#include <cstdint>

// ---------------------------------------------------------------------------
// QGCN forward on GB300 — CSR gather (edge-pipelined) + split-BF16 TC GEMM.
// ---------------------------------------------------------------------------

#define N_NODES 50000
#define N_EDGES 800000

__device__ float  g_bufA[N_NODES * 128];
__device__ float  g_bufB[N_NODES * 128];
__device__ float  g_bufC[N_NODES * 128];
__device__ int    g_deg[N_NODES];
__device__ int    g_indptr[N_NODES];
__device__ int    g_cursor[N_NODES];
__device__ float2 g_edges[N_EDGES];   // {src (bit-cast int), weight}

// ---------------------------------------------------------------------------
// BF16 helpers
// ---------------------------------------------------------------------------
__device__ __forceinline__ uint32_t pack_bf16x2(__nv_bfloat16 lo16, __nv_bfloat16 hi16) {
    __nv_bfloat162 t;
    t.x = lo16;
    t.y = hi16;
    return *reinterpret_cast<uint32_t*>(&t);
}
__device__ __forceinline__ void split_pair(float a, float b,
                                           uint32_t& wh, uint32_t& wl) {
    __nv_bfloat16 ah = __float2bfloat16_rn(a);
    __nv_bfloat16 bh = __float2bfloat16_rn(b);
    __nv_bfloat16 al = __float2bfloat16_rn(a - __bfloat162float(ah));
    __nv_bfloat16 bl = __float2bfloat16_rn(b - __bfloat162float(bh));
    wh = pack_bf16x2(ah, bh);
    wl = pack_bf16x2(al, bl);
}
__device__ __forceinline__ void mma_bf16(
    float& d0, float& d1, float& d2, float& d3,
    uint32_t a0, uint32_t a1, uint32_t a2, uint32_t a3,
    uint32_t b0, uint32_t b1)
{
    asm volatile(
        "mma.sync.aligned.m16n8k16.row.col.f32.bf16.bf16.f32 "
        "{%0,%1,%2,%3},{%4,%5,%6,%7},{%8,%9},{%0,%1,%2,%3};"
        : "+f"(d0), "+f"(d1), "+f"(d2), "+f"(d3)
        : "r"(a0), "r"(a1), "r"(a2), "r"(a3), "r"(b0), "r"(b1));
}

// ---------------------------------------------------------------------------
// GEMM: Y[N, BNT] = X[N, 128] @ W[128, BNT]   (R7 measured-good, unchanged)
// ---------------------------------------------------------------------------
template <int BNT>
__global__ __launch_bounds__(128, 4) void gemm_tc_kernel(
    const float* __restrict__ X, const float* __restrict__ W,
    float* __restrict__ Y, int N)
{
    constexpr int KC   = 32;
    constexpr int NK   = 128 / KC;
    constexpr int XSPW = 20;
    constexpr int WSPW = 72;

    __shared__ uint32_t Xh[64][XSPW], Xl[64][XSPW];
    __shared__ uint32_t Wh[16][WSPW], Wl[16][WSPW];

    const int tid  = threadIdx.x;
    const int lane = tid & 31;
    const int warp = tid >> 5;
    const int row0 = blockIdx.x * 64;
    const int nb   = blockIdx.y * 64;

    const int qr = lane >> 2;
    const int qt = lane & 3;
    const int wm = (warp & 1) * 32;
    const int wn = (warp >> 1) * 32;

    const float4* X4 = (const float4*)X;
    const float4* W4 = (const float4*)W;

    float4 xr[4];
    float4 wrA[2], wrB[2];

    auto ldgX = [&](int ch) {
#pragma unroll
        for (int i = 0; i < 4; i++) {
            int idx = tid + i * 128;
            int r = idx >> 3, c4 = idx & 7;
            int gr = row0 + r;
            xr[i] = (gr < N) ? X4[gr * 32 + ch * 8 + c4]
                             : make_float4(0.f, 0.f, 0.f, 0.f);
        }
    };
    auto ldgW = [&](int ch) {
#pragma unroll
        for (int i = 0; i < 2; i++) {
            int idx = tid + i * 128;
            int kp = idx >> 4, cc = idx & 15;
            wrA[i] = W4[(((ch * KC + 2 * kp)     * BNT + nb) >> 2) + cc];
            wrB[i] = W4[(((ch * KC + 2 * kp + 1) * BNT + nb) >> 2) + cc];
        }
    };
    auto stsX = [&]() {
#pragma unroll
        for (int i = 0; i < 4; i++) {
            int idx = tid + i * 128;
            int r = idx >> 3, c4 = idx & 7;
            uint32_t h0, l0, h1, l1;
            split_pair(xr[i].x, xr[i].y, h0, l0);
            split_pair(xr[i].z, xr[i].w, h1, l1);
            Xh[r][c4 * 2 + 0] = h0;  Xl[r][c4 * 2 + 0] = l0;
            Xh[r][c4 * 2 + 1] = h1;  Xl[r][c4 * 2 + 1] = l1;
        }
    };
    auto stsW = [&]() {
#pragma unroll
        for (int i = 0; i < 2; i++) {
            int idx = tid + i * 128;
            int kp = idx >> 4, cc = idx & 15;
            const float* a = (const float*)&wrA[i];
            const float* b = (const float*)&wrB[i];
#pragma unroll
            for (int j = 0; j < 4; j++) {
                uint32_t wh, wl;
                split_pair(a[j], b[j], wh, wl);
                Wh[kp][cc * 4 + j] = wh;
                Wl[kp][cc * 4 + j] = wl;
            }
        }
    };

    float acc[2][4][4] = {};

    ldgX(0); ldgW(0);
    stsX(); stsW();
    __syncthreads();

#pragma unroll
    for (int ch = 0; ch < NK; ch++) {
        if (ch + 1 < NK) { ldgX(ch + 1); ldgW(ch + 1); }

#pragma unroll
        for (int ks = 0; ks < 2; ks++) {
            const int kw = ks * 8 + qt;

            uint32_t ahi[2][4], alo[2][4];
#pragma unroll
            for (int mt = 0; mt < 2; mt++) {
                int r = wm + mt * 16 + qr;
                ahi[mt][0] = Xh[r][kw];
                ahi[mt][1] = Xh[r + 8][kw];
                ahi[mt][2] = Xh[r][kw + 4];
                ahi[mt][3] = Xh[r + 8][kw + 4];
                alo[mt][0] = Xl[r][kw];
                alo[mt][1] = Xl[r + 8][kw];
                alo[mt][2] = Xl[r][kw + 4];
                alo[mt][3] = Xl[r + 8][kw + 4];
            }
            uint32_t bhi[4][2], blo[4][2];
#pragma unroll
            for (int nt = 0; nt < 4; nt++) {
                int c = wn + nt * 8 + qr;
                bhi[nt][0] = Wh[ks * 8 + qt][c];
                bhi[nt][1] = Wh[ks * 8 + qt + 4][c];
                blo[nt][0] = Wl[ks * 8 + qt][c];
                blo[nt][1] = Wl[ks * 8 + qt + 4][c];
            }
#pragma unroll
            for (int mt = 0; mt < 2; mt++)
#pragma unroll
                for (int nt = 0; nt < 4; nt++) {
                    float* d = acc[mt][nt];
                    mma_bf16(d[0], d[1], d[2], d[3],
                             ahi[mt][0], ahi[mt][1], ahi[mt][2], ahi[mt][3],
                             bhi[nt][0], bhi[nt][1]);
                    mma_bf16(d[0], d[1], d[2], d[3],
                             ahi[mt][0], ahi[mt][1], ahi[mt][2], ahi[mt][3],
                             blo[nt][0], blo[nt][1]);
                    mma_bf16(d[0], d[1], d[2], d[3],
                             alo[mt][0], alo[mt][1], alo[mt][2], alo[mt][3],
                             bhi[nt][0], bhi[nt][1]);
                }
        }

        if (ch + 1 < NK) {
            __syncthreads();
            stsX(); stsW();
            __syncthreads();
        }
    }

#pragma unroll
    for (int mt = 0; mt < 2; mt++) {
#pragma unroll
        for (int nt = 0; nt < 4; nt++) {
            int gc = nb + wn + nt * 8 + qt * 2;
            int r0g = row0 + wm + mt * 16 + qr;
            if (r0g < N)
                *(float2*)&Y[r0g * BNT + gc] =
                    make_float2(acc[mt][nt][0], acc[mt][nt][1]);
            int r1g = r0g + 8;
            if (r1g < N)
                *(float2*)&Y[r1g * BNT + gc] =
                    make_float2(acc[mt][nt][2], acc[mt][nt][3]);
        }
    }
}

// ---------------------------------------------------------------------------
// CSR build
// ---------------------------------------------------------------------------
__global__ __launch_bounds__(256) void hist_kernel(
    const int* __restrict__ dst, int* __restrict__ deg, int E)
{
    int e = blockIdx.x * blockDim.x + threadIdx.x;
    if (e < E) atomicAdd(&deg[__ldg(&dst[e])], 1);
}

__global__ __launch_bounds__(1024) void scan_kernel(
    const int* __restrict__ deg, int* __restrict__ indptr,
    int* __restrict__ cursor)
{
    __shared__ int sh[1024];
    const int CHUNK = (N_NODES + 1023) / 1024;
    int t = threadIdx.x;
    int begin = t * CHUNK;
    int end   = begin + CHUNK; if (end > N_NODES) end = N_NODES;

    int s = 0;
    for (int i = begin; i < end; i++) s += deg[i];
    sh[t] = s;
    __syncthreads();

    for (int off = 1; off < 1024; off <<= 1) {
        int v = sh[t];
        int a = (t >= off) ? sh[t - off] : 0;
        __syncthreads();
        sh[t] = v + a;
        __syncthreads();
    }

    int run = (t == 0) ? 0 : sh[t - 1];
    for (int i = begin; i < end; i++) {
        indptr[i] = run;
        cursor[i] = run;
        run += deg[i];
    }
}

__global__ __launch_bounds__(256) void place_kernel(
    const int* __restrict__ src, const int* __restrict__ dst,
    const float* __restrict__ ew, int* __restrict__ cursor,
    float2* __restrict__ edges, int E)
{
    int e = blockIdx.x * blockDim.x + threadIdx.x;
    if (e >= E) return;
    int d = __ldg(&dst[e]);
    int p = atomicAdd(&cursor[d], 1);
    edges[p] = make_float2(__int_as_float(__ldg(&src[e])), __ldg(&ew[e]));
}

// ---------------------------------------------------------------------------
// Gather-aggregate, D=128: one warp per dst node, lane = float4 chunk.
// Edge descriptors software-pipelined one iteration ahead (clamped indices),
// so H gathers and next-iteration edge loads issue concurrently.
// MODE 0: val=acc+b; out0=val; out1=val+relu(val)    (layer 0)
// MODE 1: val=acc+b; out0=Bres+relu(val)             (layer 1)
// ---------------------------------------------------------------------------
template <int MODE>
__global__ __launch_bounds__(256) void gather128_kernel(
    const float* __restrict__ H, const float2* __restrict__ edges,
    const int* __restrict__ indptr, const int* __restrict__ deg,
    const float* __restrict__ bias, const float* __restrict__ Bres,
    float* __restrict__ out0, float* __restrict__ out1)
{
    int warp = (blockIdx.x * 256 + threadIdx.x) >> 5;
    int lane = threadIdx.x & 31;
    if (warp >= N_NODES) return;
    int node = warp;

    int start = __ldg(&indptr[node]);
    int cnt   = __ldg(&deg[node]);
    int last  = start + cnt - 1;      // cnt>=1 in practice; clamped loads below

    float4 acc = make_float4(0.f, 0.f, 0.f, 0.f);
    const float4* H4 = (const float4*)H;

    if (cnt > 0) {
        float2 e0 = __ldg(&edges[start]);
        float2 e1 = __ldg(&edges[min(start + 1, last)]);
        int j = 0;
        for (; j + 1 < cnt; j += 2) {
            // prefetch next edge pair (clamped — safe, values unused past end)
            float2 n0 = __ldg(&edges[min(start + j + 2, last)]);
            float2 n1 = __ldg(&edges[min(start + j + 3, last)]);
            float4 v0 = __ldg(&H4[(__float_as_int(e0.x) << 5) + lane]);
            float4 v1 = __ldg(&H4[(__float_as_int(e1.x) << 5) + lane]);
            acc.x = fmaf(v0.x, e0.y, acc.x); acc.y = fmaf(v0.y, e0.y, acc.y);
            acc.z = fmaf(v0.z, e0.y, acc.z); acc.w = fmaf(v0.w, e0.y, acc.w);
            acc.x = fmaf(v1.x, e1.y, acc.x); acc.y = fmaf(v1.y, e1.y, acc.y);
            acc.z = fmaf(v1.z, e1.y, acc.z); acc.w = fmaf(v1.w, e1.y, acc.w);
            e0 = n0; e1 = n1;
        }
        if (j < cnt) {   // odd tail: e0 already holds edges[start+j]
            float4 v0 = __ldg(&H4[(__float_as_int(e0.x) << 5) + lane]);
            acc.x = fmaf(v0.x, e0.y, acc.x); acc.y = fmaf(v0.y, e0.y, acc.y);
            acc.z = fmaf(v0.z, e0.y, acc.z); acc.w = fmaf(v0.w, e0.y, acc.w);
        }
    }

    float4 bb = ((const float4*)bias)[lane];
    float4 val = make_float4(acc.x + bb.x, acc.y + bb.y,
                             acc.z + bb.z, acc.w + bb.w);
    int idx = (node << 5) + lane;

    if (MODE == 0) {
        ((float4*)out0)[idx] = val;
        float4 c;
        c.x = val.x + fmaxf(val.x, 0.f); c.y = val.y + fmaxf(val.y, 0.f);
        c.z = val.z + fmaxf(val.z, 0.f); c.w = val.w + fmaxf(val.w, 0.f);
        ((float4*)out1)[idx] = c;
    } else {
        float4 b = __ldg(&((const float4*)Bres)[idx]);
        float4 c;
        c.x = b.x + fmaxf(val.x, 0.f); c.y = b.y + fmaxf(val.y, 0.f);
        c.z = b.z + fmaxf(val.z, 0.f); c.w = b.w + fmaxf(val.w, 0.f);
        ((float4*)out0)[idx] = c;
    }
}

// D=64: half-warp per node, same edge pipelining.
__global__ __launch_bounds__(256) void gather64_kernel(
    const float* __restrict__ H, const float2* __restrict__ edges,
    const int* __restrict__ indptr, const int* __restrict__ deg,
    const float* __restrict__ bias, float* __restrict__ out)
{
    int half = (blockIdx.x * 256 + threadIdx.x) >> 4;
    int lane = threadIdx.x & 15;
    if (half >= N_NODES) return;
    int node = half;

    int start = __ldg(&indptr[node]);
    int cnt   = __ldg(&deg[node]);
    int last  = start + cnt - 1;

    float4 acc = make_float4(0.f, 0.f, 0.f, 0.f);
    const float4* H4 = (const float4*)H;

    if (cnt > 0) {
        float2 e0 = __ldg(&edges[start]);
        float2 e1 = __ldg(&edges[min(start + 1, last)]);
        int j = 0;
        for (; j + 1 < cnt; j += 2) {
            float2 n0 = __ldg(&edges[min(start + j + 2, last)]);
            float2 n1 = __ldg(&edges[min(start + j + 3, last)]);
            float4 v0 = __ldg(&H4[(__float_as_int(e0.x) << 4) + lane]);
            float4 v1 = __ldg(&H4[(__float_as_int(e1.x) << 4) + lane]);
            acc.x = fmaf(v0.x, e0.y, acc.x); acc.y = fmaf(v0.y, e0.y, acc.y);
            acc.z = fmaf(v0.z, e0.y, acc.z); acc.w = fmaf(v0.w, e0.y, acc.w);
            acc.x = fmaf(v1.x, e1.y, acc.x); acc.y = fmaf(v1.y, e1.y, acc.y);
            acc.z = fmaf(v1.z, e1.y, acc.z); acc.w = fmaf(v1.w, e1.y, acc.w);
            e0 = n0; e1 = n1;
        }
        if (j < cnt) {
            float4 v0 = __ldg(&H4[(__float_as_int(e0.x) << 4) + lane]);
            acc.x = fmaf(v0.x, e0.y, acc.x); acc.y = fmaf(v0.y, e0.y, acc.y);
            acc.z = fmaf(v0.z, e0.y, acc.z); acc.w = fmaf(v0.w, e0.y, acc.w);
        }
    }

    float4 bb = ((const float4*)bias)[lane];
    ((float4*)out)[(node << 4) + lane] =
        make_float4(acc.x + bb.x, acc.y + bb.y, acc.z + bb.z, acc.w + bb.w);
}

// ---------------------------------------------------------------------------

extern "C" void kernel_launch(void* const* d_in, const int* in_sizes, int n_in,
                              void* d_out, int out_size)
{
    const float* x  = (const float*)d_in[0];
    const int*   ei = (const int*)d_in[1];
    const float* ea = (const float*)d_in[2];
    const float* W1 = (const float*)d_in[3];
    const float* b1 = (const float*)d_in[4];
    const float* W2 = (const float*)d_in[5];
    const float* b2 = (const float*)d_in[6];
    const float* W3 = (const float*)d_in[7];
    const float* b3 = (const float*)d_in[8];
    float* out = (float*)d_out;

    const int N = N_NODES;
    const int E = N_EDGES;
    const int* src = ei;
    const int* dst = ei + E;

    float *A, *B, *C;
    int *deg, *indptr, *cursor;
    float2* edges;
    cudaGetSymbolAddress((void**)&A, g_bufA);
    cudaGetSymbolAddress((void**)&B, g_bufB);
    cudaGetSymbolAddress((void**)&C, g_bufC);
    cudaGetSymbolAddress((void**)&deg, g_deg);
    cudaGetSymbolAddress((void**)&indptr, g_indptr);
    cudaGetSymbolAddress((void**)&cursor, g_cursor);
    cudaGetSymbolAddress((void**)&edges, g_edges);

    const int e_blocks    = (E + 255) / 256;
    const int g128_blocks = (N * 32 + 255) / 256;
    const int g64_blocks  = (N * 16 + 255) / 256;
    const int mrows       = (N + 63) / 64;          // 782

    dim3 grid128(mrows, 2);
    dim3 grid64(mrows, 1);

    // --- CSR build (reused by all 3 layers) ---
    cudaMemsetAsync(deg, 0, N * sizeof(int));
    hist_kernel<<<e_blocks, 256>>>(dst, deg, E);
    scan_kernel<<<1, 1024>>>(deg, indptr, cursor);
    place_kernel<<<e_blocks, 256>>>(src, dst, ea, cursor, edges, E);

    // --- Layer 0: B = x1 = agg(x@W1)+b1 ; C = x1 + relu(x1) ---
    gemm_tc_kernel<128><<<grid128, 128>>>(x, W1, A, N);
    gather128_kernel<0><<<g128_blocks, 256>>>(A, edges, indptr, deg, b1, nullptr, B, C);

    // --- Layer 1: C = x1 + relu(agg(C@W2)+b2) ---
    gemm_tc_kernel<128><<<grid128, 128>>>(C, W2, A, N);
    gather128_kernel<1><<<g128_blocks, 256>>>(A, edges, indptr, deg, b2, B, C, nullptr);

    // --- Layer 2: out = agg(C@W3)+b3 ---
    gemm_tc_kernel<64><<<grid64, 128>>>(C, W3, A, N);
    gather64_kernel<<<g64_blocks, 256>>>(A, edges, indptr, deg, b3, out);
}

// round 9
// speedup vs baseline: 1.3431x; 1.0118x over previous
#include <cuda_runtime.h>
#include <cuda_bf16.h>
#include <cstdint>

// ---------------------------------------------------------------------------
// QGCN forward on GB300 — CSR gather + split-BF16 TC GEMM.
// CSR build overlapped with GEMM0 via forked capture stream.
// ---------------------------------------------------------------------------

#define N_NODES 50000
#define N_EDGES 800000

__device__ float  g_bufA[N_NODES * 128];
__device__ float  g_bufB[N_NODES * 128];
__device__ float  g_bufC[N_NODES * 128];
__device__ int    g_deg[N_NODES];
__device__ int    g_indptr[N_NODES + 1];
__device__ int    g_cursor[N_NODES];
__device__ float2 g_edges[N_EDGES];   // {src (bit-cast int), weight}

// ---------------------------------------------------------------------------
// BF16 helpers
// ---------------------------------------------------------------------------
__device__ __forceinline__ uint32_t pack_bf16x2(__nv_bfloat16 lo16, __nv_bfloat16 hi16) {
    __nv_bfloat162 t;
    t.x = lo16;
    t.y = hi16;
    return *reinterpret_cast<uint32_t*>(&t);
}
__device__ __forceinline__ void split_pair(float a, float b,
                                           uint32_t& wh, uint32_t& wl) {
    __nv_bfloat16 ah = __float2bfloat16_rn(a);
    __nv_bfloat16 bh = __float2bfloat16_rn(b);
    __nv_bfloat16 al = __float2bfloat16_rn(a - __bfloat162float(ah));
    __nv_bfloat16 bl = __float2bfloat16_rn(b - __bfloat162float(bh));
    wh = pack_bf16x2(ah, bh);
    wl = pack_bf16x2(al, bl);
}
__device__ __forceinline__ void mma_bf16(
    float& d0, float& d1, float& d2, float& d3,
    uint32_t a0, uint32_t a1, uint32_t a2, uint32_t a3,
    uint32_t b0, uint32_t b1)
{
    asm volatile(
        "mma.sync.aligned.m16n8k16.row.col.f32.bf16.bf16.f32 "
        "{%0,%1,%2,%3},{%4,%5,%6,%7},{%8,%9},{%0,%1,%2,%3};"
        : "+f"(d0), "+f"(d1), "+f"(d2), "+f"(d3)
        : "r"(a0), "r"(a1), "r"(a2), "r"(a3), "r"(b0), "r"(b1));
}

// ---------------------------------------------------------------------------
// GEMM: Y[N, BNT] = X[N, 128] @ W[128, BNT]   (R7 measured-good, unchanged)
// ---------------------------------------------------------------------------
template <int BNT>
__global__ __launch_bounds__(128, 4) void gemm_tc_kernel(
    const float* __restrict__ X, const float* __restrict__ W,
    float* __restrict__ Y, int N)
{
    constexpr int KC   = 32;
    constexpr int NK   = 128 / KC;
    constexpr int XSPW = 20;
    constexpr int WSPW = 72;

    __shared__ uint32_t Xh[64][XSPW], Xl[64][XSPW];
    __shared__ uint32_t Wh[16][WSPW], Wl[16][WSPW];

    const int tid  = threadIdx.x;
    const int lane = tid & 31;
    const int warp = tid >> 5;
    const int row0 = blockIdx.x * 64;
    const int nb   = blockIdx.y * 64;

    const int qr = lane >> 2;
    const int qt = lane & 3;
    const int wm = (warp & 1) * 32;
    const int wn = (warp >> 1) * 32;

    const float4* X4 = (const float4*)X;
    const float4* W4 = (const float4*)W;

    float4 xr[4];
    float4 wrA[2], wrB[2];

    auto ldgX = [&](int ch) {
#pragma unroll
        for (int i = 0; i < 4; i++) {
            int idx = tid + i * 128;
            int r = idx >> 3, c4 = idx & 7;
            int gr = row0 + r;
            xr[i] = (gr < N) ? X4[gr * 32 + ch * 8 + c4]
                             : make_float4(0.f, 0.f, 0.f, 0.f);
        }
    };
    auto ldgW = [&](int ch) {
#pragma unroll
        for (int i = 0; i < 2; i++) {
            int idx = tid + i * 128;
            int kp = idx >> 4, cc = idx & 15;
            wrA[i] = W4[(((ch * KC + 2 * kp)     * BNT + nb) >> 2) + cc];
            wrB[i] = W4[(((ch * KC + 2 * kp + 1) * BNT + nb) >> 2) + cc];
        }
    };
    auto stsX = [&]() {
#pragma unroll
        for (int i = 0; i < 4; i++) {
            int idx = tid + i * 128;
            int r = idx >> 3, c4 = idx & 7;
            uint32_t h0, l0, h1, l1;
            split_pair(xr[i].x, xr[i].y, h0, l0);
            split_pair(xr[i].z, xr[i].w, h1, l1);
            Xh[r][c4 * 2 + 0] = h0;  Xl[r][c4 * 2 + 0] = l0;
            Xh[r][c4 * 2 + 1] = h1;  Xl[r][c4 * 2 + 1] = l1;
        }
    };
    auto stsW = [&]() {
#pragma unroll
        for (int i = 0; i < 2; i++) {
            int idx = tid + i * 128;
            int kp = idx >> 4, cc = idx & 15;
            const float* a = (const float*)&wrA[i];
            const float* b = (const float*)&wrB[i];
#pragma unroll
            for (int j = 0; j < 4; j++) {
                uint32_t wh, wl;
                split_pair(a[j], b[j], wh, wl);
                Wh[kp][cc * 4 + j] = wh;
                Wl[kp][cc * 4 + j] = wl;
            }
        }
    };

    float acc[2][4][4] = {};

    ldgX(0); ldgW(0);
    stsX(); stsW();
    __syncthreads();

#pragma unroll
    for (int ch = 0; ch < NK; ch++) {
        if (ch + 1 < NK) { ldgX(ch + 1); ldgW(ch + 1); }

#pragma unroll
        for (int ks = 0; ks < 2; ks++) {
            const int kw = ks * 8 + qt;

            uint32_t ahi[2][4], alo[2][4];
#pragma unroll
            for (int mt = 0; mt < 2; mt++) {
                int r = wm + mt * 16 + qr;
                ahi[mt][0] = Xh[r][kw];
                ahi[mt][1] = Xh[r + 8][kw];
                ahi[mt][2] = Xh[r][kw + 4];
                ahi[mt][3] = Xh[r + 8][kw + 4];
                alo[mt][0] = Xl[r][kw];
                alo[mt][1] = Xl[r + 8][kw];
                alo[mt][2] = Xl[r][kw + 4];
                alo[mt][3] = Xl[r + 8][kw + 4];
            }
            uint32_t bhi[4][2], blo[4][2];
#pragma unroll
            for (int nt = 0; nt < 4; nt++) {
                int c = wn + nt * 8 + qr;
                bhi[nt][0] = Wh[ks * 8 + qt][c];
                bhi[nt][1] = Wh[ks * 8 + qt + 4][c];
                blo[nt][0] = Wl[ks * 8 + qt][c];
                blo[nt][1] = Wl[ks * 8 + qt + 4][c];
            }
#pragma unroll
            for (int mt = 0; mt < 2; mt++)
#pragma unroll
                for (int nt = 0; nt < 4; nt++) {
                    float* d = acc[mt][nt];
                    mma_bf16(d[0], d[1], d[2], d[3],
                             ahi[mt][0], ahi[mt][1], ahi[mt][2], ahi[mt][3],
                             bhi[nt][0], bhi[nt][1]);
                    mma_bf16(d[0], d[1], d[2], d[3],
                             ahi[mt][0], ahi[mt][1], ahi[mt][2], ahi[mt][3],
                             blo[nt][0], blo[nt][1]);
                    mma_bf16(d[0], d[1], d[2], d[3],
                             alo[mt][0], alo[mt][1], alo[mt][2], alo[mt][3],
                             bhi[nt][0], bhi[nt][1]);
                }
        }

        if (ch + 1 < NK) {
            __syncthreads();
            stsX(); stsW();
            __syncthreads();
        }
    }

#pragma unroll
    for (int mt = 0; mt < 2; mt++) {
#pragma unroll
        for (int nt = 0; nt < 4; nt++) {
            int gc = nb + wn + nt * 8 + qt * 2;
            int r0g = row0 + wm + mt * 16 + qr;
            if (r0g < N)
                *(float2*)&Y[r0g * BNT + gc] =
                    make_float2(acc[mt][nt][0], acc[mt][nt][1]);
            int r1g = r0g + 8;
            if (r1g < N)
                *(float2*)&Y[r1g * BNT + gc] =
                    make_float2(acc[mt][nt][2], acc[mt][nt][3]);
        }
    }
}

// ---------------------------------------------------------------------------
// CSR build
// ---------------------------------------------------------------------------
__global__ __launch_bounds__(256) void hist_kernel(
    const int* __restrict__ dst, int* __restrict__ deg, int E)
{
    int e = blockIdx.x * blockDim.x + threadIdx.x;
    if (e < E) atomicAdd(&deg[__ldg(&dst[e])], 1);
}

__global__ __launch_bounds__(1024) void scan_kernel(
    const int* __restrict__ deg, int* __restrict__ indptr,
    int* __restrict__ cursor)
{
    __shared__ int sh[1024];
    const int CHUNK = (N_NODES + 1023) / 1024;
    int t = threadIdx.x;
    int begin = t * CHUNK;
    int end   = begin + CHUNK; if (end > N_NODES) end = N_NODES;

    int s = 0;
    for (int i = begin; i < end; i++) s += deg[i];
    sh[t] = s;
    __syncthreads();

    for (int off = 1; off < 1024; off <<= 1) {
        int v = sh[t];
        int a = (t >= off) ? sh[t - off] : 0;
        __syncthreads();
        sh[t] = v + a;
        __syncthreads();
    }

    int run = (t == 0) ? 0 : sh[t - 1];
    for (int i = begin; i < end; i++) {
        indptr[i] = run;
        cursor[i] = run;
        run += deg[i];
    }
    if (t == 1023) indptr[N_NODES] = run;
}

__global__ __launch_bounds__(256) void place_kernel(
    const int* __restrict__ src, const int* __restrict__ dst,
    const float* __restrict__ ew, int* __restrict__ cursor,
    float2* __restrict__ edges, int E)
{
    int e = blockIdx.x * blockDim.x + threadIdx.x;
    if (e >= E) return;
    int d = __ldg(&dst[e]);
    int p = atomicAdd(&cursor[d], 1);
    edges[p] = make_float2(__int_as_float(__ldg(&src[e])), __ldg(&ew[e]));
}

// ---------------------------------------------------------------------------
// Gather-aggregate, D=128: one warp per dst node, lane = float4 chunk.
// MODE 0: val=acc+b; out0=val; out1=val+relu(val)    (layer 0)
// MODE 1: val=acc+b; out0=Bres+relu(val)             (layer 1)
// ---------------------------------------------------------------------------
template <int MODE>
__global__ __launch_bounds__(256) void gather128_kernel(
    const float* __restrict__ H, const float2* __restrict__ edges,
    const int* __restrict__ indptr,
    const float* __restrict__ bias, const float* __restrict__ Bres,
    float* __restrict__ out0, float* __restrict__ out1)
{
    int warp = (blockIdx.x * 256 + threadIdx.x) >> 5;
    int lane = threadIdx.x & 31;
    if (warp >= N_NODES) return;
    int node = warp;

    int start = __ldg(&indptr[node]);
    int endp  = __ldg(&indptr[node + 1]);
    int cnt   = endp - start;
    int last  = endp - 1;

    float4 acc = make_float4(0.f, 0.f, 0.f, 0.f);
    const float4* H4 = (const float4*)H;

    if (cnt > 0) {
        float2 e0 = __ldg(&edges[start]);
        float2 e1 = __ldg(&edges[min(start + 1, last)]);
        int j = 0;
        for (; j + 1 < cnt; j += 2) {
            float2 n0 = __ldg(&edges[min(start + j + 2, last)]);
            float2 n1 = __ldg(&edges[min(start + j + 3, last)]);
            float4 v0 = __ldg(&H4[(__float_as_int(e0.x) << 5) + lane]);
            float4 v1 = __ldg(&H4[(__float_as_int(e1.x) << 5) + lane]);
            acc.x = fmaf(v0.x, e0.y, acc.x); acc.y = fmaf(v0.y, e0.y, acc.y);
            acc.z = fmaf(v0.z, e0.y, acc.z); acc.w = fmaf(v0.w, e0.y, acc.w);
            acc.x = fmaf(v1.x, e1.y, acc.x); acc.y = fmaf(v1.y, e1.y, acc.y);
            acc.z = fmaf(v1.z, e1.y, acc.z); acc.w = fmaf(v1.w, e1.y, acc.w);
            e0 = n0; e1 = n1;
        }
        if (j < cnt) {
            float4 v0 = __ldg(&H4[(__float_as_int(e0.x) << 5) + lane]);
            acc.x = fmaf(v0.x, e0.y, acc.x); acc.y = fmaf(v0.y, e0.y, acc.y);
            acc.z = fmaf(v0.z, e0.y, acc.z); acc.w = fmaf(v0.w, e0.y, acc.w);
        }
    }

    float4 bb = ((const float4*)bias)[lane];
    float4 val = make_float4(acc.x + bb.x, acc.y + bb.y,
                             acc.z + bb.z, acc.w + bb.w);
    int idx = (node << 5) + lane;

    if (MODE == 0) {
        ((float4*)out0)[idx] = val;
        float4 c;
        c.x = val.x + fmaxf(val.x, 0.f); c.y = val.y + fmaxf(val.y, 0.f);
        c.z = val.z + fmaxf(val.z, 0.f); c.w = val.w + fmaxf(val.w, 0.f);
        ((float4*)out1)[idx] = c;
    } else {
        float4 b = __ldg(&((const float4*)Bres)[idx]);
        float4 c;
        c.x = b.x + fmaxf(val.x, 0.f); c.y = b.y + fmaxf(val.y, 0.f);
        c.z = b.z + fmaxf(val.z, 0.f); c.w = b.w + fmaxf(val.w, 0.f);
        ((float4*)out0)[idx] = c;
    }
}

// D=64: half-warp per node.
__global__ __launch_bounds__(256) void gather64_kernel(
    const float* __restrict__ H, const float2* __restrict__ edges,
    const int* __restrict__ indptr,
    const float* __restrict__ bias, float* __restrict__ out)
{
    int half = (blockIdx.x * 256 + threadIdx.x) >> 4;
    int lane = threadIdx.x & 15;
    if (half >= N_NODES) return;
    int node = half;

    int start = __ldg(&indptr[node]);
    int endp  = __ldg(&indptr[node + 1]);
    int cnt   = endp - start;
    int last  = endp - 1;

    float4 acc = make_float4(0.f, 0.f, 0.f, 0.f);
    const float4* H4 = (const float4*)H;

    if (cnt > 0) {
        float2 e0 = __ldg(&edges[start]);
        float2 e1 = __ldg(&edges[min(start + 1, last)]);
        int j = 0;
        for (; j + 1 < cnt; j += 2) {
            float2 n0 = __ldg(&edges[min(start + j + 2, last)]);
            float2 n1 = __ldg(&edges[min(start + j + 3, last)]);
            float4 v0 = __ldg(&H4[(__float_as_int(e0.x) << 4) + lane]);
            float4 v1 = __ldg(&H4[(__float_as_int(e1.x) << 4) + lane]);
            acc.x = fmaf(v0.x, e0.y, acc.x); acc.y = fmaf(v0.y, e0.y, acc.y);
            acc.z = fmaf(v0.z, e0.y, acc.z); acc.w = fmaf(v0.w, e0.y, acc.w);
            acc.x = fmaf(v1.x, e1.y, acc.x); acc.y = fmaf(v1.y, e1.y, acc.y);
            acc.z = fmaf(v1.z, e1.y, acc.z); acc.w = fmaf(v1.w, e1.y, acc.w);
            e0 = n0; e1 = n1;
        }
        if (j < cnt) {
            float4 v0 = __ldg(&H4[(__float_as_int(e0.x) << 4) + lane]);
            acc.x = fmaf(v0.x, e0.y, acc.x); acc.y = fmaf(v0.y, e0.y, acc.y);
            acc.z = fmaf(v0.z, e0.y, acc.z); acc.w = fmaf(v0.w, e0.y, acc.w);
        }
    }

    float4 bb = ((const float4*)bias)[lane];
    ((float4*)out)[(node << 4) + lane] =
        make_float4(acc.x + bb.x, acc.y + bb.y, acc.z + bb.z, acc.w + bb.w);
}

// ---------------------------------------------------------------------------

extern "C" void kernel_launch(void* const* d_in, const int* in_sizes, int n_in,
                              void* d_out, int out_size)
{
    const float* x  = (const float*)d_in[0];
    const int*   ei = (const int*)d_in[1];
    const float* ea = (const float*)d_in[2];
    const float* W1 = (const float*)d_in[3];
    const float* b1 = (const float*)d_in[4];
    const float* W2 = (const float*)d_in[5];
    const float* b2 = (const float*)d_in[6];
    const float* W3 = (const float*)d_in[7];
    const float* b3 = (const float*)d_in[8];
    float* out = (float*)d_out;

    const int N = N_NODES;
    const int E = N_EDGES;
    const int* src = ei;
    const int* dst = ei + E;

    float *A, *B, *C;
    int *deg, *indptr, *cursor;
    float2* edges;
    cudaGetSymbolAddress((void**)&A, g_bufA);
    cudaGetSymbolAddress((void**)&B, g_bufB);
    cudaGetSymbolAddress((void**)&C, g_bufC);
    cudaGetSymbolAddress((void**)&deg, g_deg);
    cudaGetSymbolAddress((void**)&indptr, g_indptr);
    cudaGetSymbolAddress((void**)&cursor, g_cursor);
    cudaGetSymbolAddress((void**)&edges, g_edges);

    const int e_blocks    = (E + 255) / 256;
    const int g128_blocks = (N * 32 + 255) / 256;
    const int g64_blocks  = (N * 16 + 255) / 256;
    const int mrows       = (N + 63) / 64;          // 782

    dim3 grid128(mrows, 2);
    dim3 grid64(mrows, 1);

    // Side stream + fork/join events (host objects; created per call so every
    // call performs identical device work; no device memory involved).
    cudaStream_t s2;
    cudaStreamCreateWithFlags(&s2, cudaStreamNonBlocking);
    cudaEvent_t evFork, evJoin;
    cudaEventCreateWithFlags(&evFork, cudaEventDisableTiming);
    cudaEventCreateWithFlags(&evJoin, cudaEventDisableTiming);

    // --- Fork: CSR build on s2, GEMM0 on main stream, concurrently ---
    cudaEventRecord(evFork, 0);
    cudaStreamWaitEvent(s2, evFork, 0);

    cudaMemsetAsync(deg, 0, N * sizeof(int), s2);
    hist_kernel<<<e_blocks, 256, 0, s2>>>(dst, deg, E);
    scan_kernel<<<1, 1024, 0, s2>>>(deg, indptr, cursor);
    place_kernel<<<e_blocks, 256, 0, s2>>>(src, dst, ea, cursor, edges, E);
    cudaEventRecord(evJoin, s2);

    gemm_tc_kernel<128><<<grid128, 128>>>(x, W1, A, N);   // main stream

    // --- Join: gathers need both GEMM0 and the CSR ---
    cudaStreamWaitEvent(0, evJoin, 0);

    // --- Layer 0: B = x1 = agg(x@W1)+b1 ; C = x1 + relu(x1) ---
    gather128_kernel<0><<<g128_blocks, 256>>>(A, edges, indptr, b1, nullptr, B, C);

    // --- Layer 1: C = x1 + relu(agg(C@W2)+b2) ---
    gemm_tc_kernel<128><<<grid128, 128>>>(C, W2, A, N);
    gather128_kernel<1><<<g128_blocks, 256>>>(A, edges, indptr, b2, B, C, nullptr);

    // --- Layer 2: out = agg(C@W3)+b3 ---
    gemm_tc_kernel<64><<<grid64, 128>>>(C, W3, A, N);
    gather64_kernel<<<g64_blocks, 256>>>(A, edges, indptr, b3, out);
}